// round 1
// baseline (speedup 1.0000x reference)
#include <cuda_runtime.h>
#include <cuda_bf16.h>
#include <math.h>

// ---------------- problem dims ----------------
#define BATCH   2
#define LEN     1024
#define DM      1024      // d_model
#define DI      2048      // d_inner
#define DS      16        // d_state
#define DTR     64        // dt_rank
#define DCONV   4
#define TOK     (BATCH*LEN)   // 2048 tokens
#define DBC_W   (DTR + 2*DS)  // 96

// ---------------- scratch (device globals; no allocation allowed) ----------------
__device__ float g_xn [TOK*DM];        // ln1 output
__device__ float g_xz [TOK*2*DI];      // in_proj output (u | z)
__device__ float g_uc [TOK*DI];        // conv+silu output
__device__ float g_dbc[TOK*DBC_W];     // x_proj output (dt | B | C)
__device__ float g_dl [TOK*DI];        // delta = softplus(dt_proj)
__device__ float g_yg [TOK*DI];        // gated scan output
__device__ float g_h  [TOK*DM];        // residual after mamba
__device__ float g_yn [TOK*DM];        // ln2 output
__device__ float g_mid[TOK*2*DM];      // mlp intermediate

// ---------------- helpers ----------------
__device__ __forceinline__ float siluf(float x) {
    return x / (1.0f + __expf(-x));
}
__device__ __forceinline__ float softplusf(float x) {
    // stable: max(x,0) + log1p(exp(-|x|))
    return fmaxf(x, 0.0f) + log1pf(expf(-fabsf(x)));
}
__device__ __forceinline__ float geluf(float x) {
    return 0.5f * x * (1.0f + erff(x * 0.70710678118654752f));
}
__device__ __forceinline__ float warp_sum(float v) {
    #pragma unroll
    for (int o = 16; o > 0; o >>= 1) v += __shfl_xor_sync(0xffffffffu, v, o);
    return v;
}

// ---------------- layernorm (block per row of DM) ----------------
__global__ __launch_bounds__(256) void layernorm_k(
    const float* __restrict__ x, const float* __restrict__ w,
    const float* __restrict__ b, float* __restrict__ out)
{
    int row = blockIdx.x;
    const float* xr = x + (size_t)row * DM;
    float s = 0.f, s2 = 0.f;
    #pragma unroll
    for (int i = threadIdx.x; i < DM; i += 256) {
        float v = xr[i];
        s += v; s2 += v * v;
    }
    __shared__ float sh1[8], sh2[8];
    int wid = threadIdx.x >> 5, lid = threadIdx.x & 31;
    s = warp_sum(s); s2 = warp_sum(s2);
    if (lid == 0) { sh1[wid] = s; sh2[wid] = s2; }
    __syncthreads();
    if (wid == 0) {
        float a = (lid < 8) ? sh1[lid] : 0.f;
        float c = (lid < 8) ? sh2[lid] : 0.f;
        a = warp_sum(a); c = warp_sum(c);
        if (lid == 0) { sh1[0] = a; sh2[0] = c; }
    }
    __syncthreads();
    float mean = sh1[0] * (1.0f / DM);
    float var  = sh2[0] * (1.0f / DM) - mean * mean;
    float inv  = rsqrtf(var + 1e-5f);
    float* orow = out + (size_t)row * DM;
    for (int i = threadIdx.x; i < DM; i += 256)
        orow[i] = (xr[i] - mean) * inv * w[i] + b[i];
}

// ---------------- tiled GEMM: C[M,N] = act(A[M,K] * W[N,K]^T + bias) + res ----------------
// ACT: 0 none, 1 softplus, 2 gelu
#define BM 128
#define BN 128
#define BK 8
#define TM 8
#define TN 8

template<int ACT, bool RES>
__global__ __launch_bounds__(256) void gemm_k(
    const float* __restrict__ A, int lda,
    const float* __restrict__ W, int ldw,
    const float* __restrict__ bias,
    const float* __restrict__ res, int ldr,
    float* __restrict__ C, int ldc,
    int M, int N, int K)
{
    __shared__ float As[BK][BM];
    __shared__ float Ws[BK][BN];
    const int bm = blockIdx.y * BM;
    const int bn = blockIdx.x * BN;
    const int tid = threadIdx.x;
    const int tx = tid & 15;   // 0..15 -> N
    const int ty = tid >> 4;   // 0..15 -> M

    float acc[TM][TN];
    #pragma unroll
    for (int i = 0; i < TM; i++)
        #pragma unroll
        for (int j = 0; j < TN; j++) acc[i][j] = 0.f;

    for (int k0 = 0; k0 < K; k0 += BK) {
        #pragma unroll
        for (int i = 0; i < 4; i++) {
            int idx = tid + i * 256;       // 0..1023
            int r = idx >> 3, c = idx & 7; // r 0..127, c 0..7 (K always %8==0)
            int gm = bm + r, gn = bn + r, gk = k0 + c;
            As[c][r] = (gm < M) ? A[(size_t)gm * lda + gk] : 0.f;
            Ws[c][r] = (gn < N) ? W[(size_t)gn * ldw + gk] : 0.f;
        }
        __syncthreads();
        #pragma unroll
        for (int k = 0; k < BK; k++) {
            float ra[TM], rb[TN];
            #pragma unroll
            for (int i = 0; i < TM; i++) ra[i] = As[k][ty * TM + i];
            #pragma unroll
            for (int j = 0; j < TN; j++) rb[j] = Ws[k][tx * TN + j];
            #pragma unroll
            for (int i = 0; i < TM; i++)
                #pragma unroll
                for (int j = 0; j < TN; j++)
                    acc[i][j] = fmaf(ra[i], rb[j], acc[i][j]);
        }
        __syncthreads();
    }

    #pragma unroll
    for (int i = 0; i < TM; i++) {
        int m = bm + ty * TM + i;
        if (m >= M) continue;
        #pragma unroll
        for (int j = 0; j < TN; j++) {
            int n = bn + tx * TN + j;
            if (n >= N) continue;
            float v = acc[i][j];
            if (bias) v += bias[n];
            if (ACT == 1) v = softplusf(v);
            if (ACT == 2) v = geluf(v);
            if (RES) v += res[(size_t)m * ldr + n];
            C[(size_t)m * ldc + n] = v;
        }
    }
}

// ---------------- depthwise causal conv (width 4) + bias + silu ----------------
// input: u = g_xz[:, 0:DI]  (token-major, stride 2*DI); output g_uc (stride DI)
__global__ __launch_bounds__(256) void conv_silu_k(
    const float* __restrict__ xz, const float* __restrict__ cw,
    const float* __restrict__ cb, float* __restrict__ uc)
{
    int idx = blockIdx.x * 256 + threadIdx.x;     // over TOK*DI
    if (idx >= TOK * DI) return;
    int d = idx & (DI - 1);
    int t = idx >> 11;            // token index (b*LEN + l)
    int l = t & (LEN - 1);
    float acc = cb[d];
    #pragma unroll
    for (int j = 0; j < DCONV; j++) {
        int ls = l - (DCONV - 1) + j;
        if (ls >= 0)
            acc = fmaf(cw[d * DCONV + j], xz[(size_t)(t - (DCONV - 1) + j) * (2 * DI) + d], acc);
    }
    uc[idx] = siluf(acc);
}

// ---------------- selective scan + skip (u*D) + gate silu(z) ----------------
// one thread per (b, d); 16 states in registers
__global__ __launch_bounds__(256) void scan_k(
    const float* __restrict__ delta,   // [TOK, DI]
    const float* __restrict__ uc,      // [TOK, DI]
    const float* __restrict__ dbc,     // [TOK, 96]  (dt | B | C)
    const float* __restrict__ xz,      // [TOK, 2*DI] (z at +DI)
    const float* __restrict__ A_log,   // [DI, DS]
    const float* __restrict__ Dp,      // [DI]
    float* __restrict__ yg)            // [TOK, DI]
{
    int d = blockIdx.x * 256 + threadIdx.x;   // 0..DI-1
    int b = blockIdx.y;
    if (d >= DI) return;

    float Ar[DS];
    #pragma unroll
    for (int n = 0; n < DS; n++) Ar[n] = -expf(A_log[d * DS + n]);
    float Dd = Dp[d];

    float h[DS];
    #pragma unroll
    for (int n = 0; n < DS; n++) h[n] = 0.f;

    for (int l = 0; l < LEN; l++) {
        int t = b * LEN + l;
        float dl = delta[(size_t)t * DI + d];
        float u  = uc[(size_t)t * DI + d];
        const float* BC = dbc + (size_t)t * DBC_W + DTR;
        float du = dl * u;
        float y = 0.f;
        #pragma unroll
        for (int n = 0; n < DS; n++) {
            float dA = __expf(dl * Ar[n]);
            h[n] = fmaf(dA, h[n], du * BC[n]);        // BC[n] = B[n]
            y    = fmaf(h[n], BC[DS + n], y);          // BC[DS+n] = C[n]
        }
        y = fmaf(u, Dd, y);
        float z = xz[(size_t)t * (2 * DI) + DI + d];
        yg[(size_t)t * DI + d] = y * siluf(z);
    }
}

// ---------------- launch ----------------
static float* sym(const void* s) {
    void* p = nullptr;
    cudaGetSymbolAddress(&p, s);
    return (float*)p;
}

extern "C" void kernel_launch(void* const* d_in, const int* in_sizes, int n_in,
                              void* d_out, int out_size)
{
    const float* x         = (const float*)d_in[0];
    const float* ln1_w     = (const float*)d_in[1];
    const float* ln1_b     = (const float*)d_in[2];
    const float* in_proj_w = (const float*)d_in[3];   // (4096, 1024)
    const float* conv_w    = (const float*)d_in[4];   // (2048, 1, 4)
    const float* conv_b    = (const float*)d_in[5];
    const float* x_proj_w  = (const float*)d_in[6];   // (96, 2048)
    const float* dt_proj_w = (const float*)d_in[7];   // (2048, 64)
    const float* dt_proj_b = (const float*)d_in[8];
    const float* A_log     = (const float*)d_in[9];   // (2048, 16)
    const float* Dp        = (const float*)d_in[10];
    const float* out_proj_w= (const float*)d_in[11];  // (1024, 2048)
    const float* ln2_w     = (const float*)d_in[12];
    const float* ln2_b     = (const float*)d_in[13];
    const float* mlp_w1    = (const float*)d_in[14];  // (2048, 1024)
    const float* mlp_b1    = (const float*)d_in[15];
    const float* mlp_w2    = (const float*)d_in[16];  // (1024, 2048)
    const float* mlp_b2    = (const float*)d_in[17];
    float* out = (float*)d_out;

    float* xn  = sym(g_xn);
    float* xz  = sym(g_xz);
    float* uc  = sym(g_uc);
    float* dbc = sym(g_dbc);
    float* dl  = sym(g_dl);
    float* yg  = sym(g_yg);
    float* h   = sym(g_h);
    float* yn  = sym(g_yn);
    float* mid = sym(g_mid);

    // 1) ln1(x) -> xn
    layernorm_k<<<TOK, 256>>>(x, ln1_w, ln1_b, xn);

    // 2) xz = xn @ in_proj_w^T : M=2048, N=4096, K=1024
    {
        dim3 grid((2 * DI + BN - 1) / BN, (TOK + BM - 1) / BM);
        gemm_k<0, false><<<grid, 256>>>(xn, DM, in_proj_w, DM, nullptr, nullptr, 0,
                                        xz, 2 * DI, TOK, 2 * DI, DM);
    }

    // 3) causal depthwise conv + silu on u (= xz[:, :DI]) -> uc
    conv_silu_k<<<(TOK * DI) / 256, 256>>>(xz, conv_w, conv_b, uc);

    // 4) dbc = uc @ x_proj_w^T : M=2048, N=96, K=2048
    {
        dim3 grid((DBC_W + BN - 1) / BN, (TOK + BM - 1) / BM);
        gemm_k<0, false><<<grid, 256>>>(uc, DI, x_proj_w, DI, nullptr, nullptr, 0,
                                        dbc, DBC_W, TOK, DBC_W, DI);
    }

    // 5) delta = softplus(dt @ dt_proj_w^T + b) : M=2048, N=2048, K=64 (dt = dbc[:, :64], lda=96)
    {
        dim3 grid((DI + BN - 1) / BN, (TOK + BM - 1) / BM);
        gemm_k<1, false><<<grid, 256>>>(dbc, DBC_W, dt_proj_w, DTR, dt_proj_b, nullptr, 0,
                                        dl, DI, TOK, DI, DTR);
    }

    // 6) selective scan + skip + gate -> yg
    {
        dim3 grid(DI / 256, BATCH);
        scan_k<<<grid, 256>>>(dl, uc, dbc, xz, A_log, Dp, yg);
    }

    // 7) h = x + yg @ out_proj_w^T : M=2048, N=1024, K=2048
    {
        dim3 grid((DM + BN - 1) / BN, (TOK + BM - 1) / BM);
        gemm_k<0, true><<<grid, 256>>>(yg, DI, out_proj_w, DI, nullptr, x, DM,
                                       h, DM, TOK, DM, DI);
    }

    // 8) ln2(h) -> yn
    layernorm_k<<<TOK, 256>>>(h, ln2_w, ln2_b, yn);

    // 9) mid = gelu(yn @ mlp_w1^T + b1) : M=2048, N=2048, K=1024
    {
        dim3 grid((2 * DM + BN - 1) / BN, (TOK + BM - 1) / BM);
        gemm_k<2, false><<<grid, 256>>>(yn, DM, mlp_w1, DM, mlp_b1, nullptr, 0,
                                        mid, 2 * DM, TOK, 2 * DM, DM);
    }

    // 10) out = h + mid @ mlp_w2^T + b2 : M=2048, N=1024, K=2048
    {
        dim3 grid((DM + BN - 1) / BN, (TOK + BM - 1) / BM);
        gemm_k<0, true><<<grid, 256>>>(mid, 2 * DM, mlp_w2, 2 * DM, mlp_b2, h, DM,
                                       out, DM, TOK, DM, 2 * DM);
    }
}